// round 11
// baseline (speedup 1.0000x reference)
#include <cuda_runtime.h>

#define NN 50000
#define NE 800000
#define NDIM 128
#define HID 64
#define EDIM 16

// ---------------- scratch (device globals; no allocation allowed) ----------
__device__ __align__(16) float g_Hn[NN * HID];     // (X@W) * dinv[row]
__device__ __align__(16) float g_Acc[NN * HID];    // aggregation accumulator
__device__ __align__(16) float g_AB[NN * 128];     // [A | B] per node for edge MLP
__device__ int g_deg[NN];

// ---------------- vector reduction helper ----------------------------------
__device__ __forceinline__ void red_add_v4(float* p, float4 v) {
    asm volatile("red.global.add.v4.f32 [%0], {%1,%2,%3,%4};"
                 :: "l"(p), "f"(v.x), "f"(v.y), "f"(v.z), "f"(v.w)
                 : "memory");
}

// ---------------- degree kernels -------------------------------------------
__global__ void k_deg_init(int* deg) {
    int i = blockIdx.x * blockDim.x + threadIdx.x;
    if (i < NN) deg[i] = 1;   // self-loop
}
__global__ void k_deg_count(const int* __restrict__ ei, int* deg) {
    int e = blockIdx.x * blockDim.x + threadIdx.x;
    if (e < NE) atomicAdd(&deg[ei[NE + e]], 1);
}

// ---------------- GEMM: Out = [relu(X+b)] @ W[K,64] ------------------------
// 128x64 tile, 256 threads, 8x4 microtile, K chunked by 32.
template <int K, bool IN_RELU>
__global__ void __launch_bounds__(256, 3)
k_gemm(const float* __restrict__ X, const float* __restrict__ W,
       const float* __restrict__ inb, const int* __restrict__ deg,
       float* __restrict__ OutA, float* __restrict__ OutB) {
    __shared__ float sX[32][132];   // [k][row], 16B-aligned stride
    __shared__ float sW[32][64];    // [k][col]
    int t  = threadIdx.x;
    int br = blockIdx.x * 128;
    int tx = t & 15, ty = t >> 4;
    float acc[8][4] = {};

    for (int kc = 0; kc < K; kc += 32) {
        #pragma unroll
        for (int i = 0; i < 4; i++) {
            int id = t + i * 256;
            int r  = id >> 3;
            int kb = (id & 7) * 4;
            int row = br + r;
            float4 v = make_float4(0.f, 0.f, 0.f, 0.f);
            if (row < NN) {
                v = *(const float4*)&X[row * K + kc + kb];
                if (IN_RELU) {
                    v.x = fmaxf(v.x + inb[kc + kb + 0], 0.f);
                    v.y = fmaxf(v.y + inb[kc + kb + 1], 0.f);
                    v.z = fmaxf(v.z + inb[kc + kb + 2], 0.f);
                    v.w = fmaxf(v.w + inb[kc + kb + 3], 0.f);
                }
            }
            sX[kb + 0][r] = v.x;
            sX[kb + 1][r] = v.y;
            sX[kb + 2][r] = v.z;
            sX[kb + 3][r] = v.w;
        }
        #pragma unroll
        for (int i = 0; i < 2; i++) {
            int id = t + i * 256;
            int kk = id >> 4, c4 = (id & 15) * 4;
            *(float4*)&sW[kk][c4] = *(const float4*)&W[(kc + kk) * 64 + c4];
        }
        __syncthreads();
        #pragma unroll
        for (int kk = 0; kk < 32; kk++) {
            float a[8], b[4];
            *(float4*)&a[0] = *(const float4*)&sX[kk][ty * 8];
            *(float4*)&a[4] = *(const float4*)&sX[kk][ty * 8 + 4];
            *(float4*)&b[0] = *(const float4*)&sW[kk][tx * 4];
            #pragma unroll
            for (int i2 = 0; i2 < 8; i2++)
                #pragma unroll
                for (int j = 0; j < 4; j++)
                    acc[i2][j] += a[i2] * b[j];
        }
        __syncthreads();
    }
    #pragma unroll
    for (int i2 = 0; i2 < 8; i2++) {
        int row = br + ty * 8 + i2;
        if (row < NN) {
            float d = rsqrtf((float)deg[row]);
            float4 hn = make_float4(acc[i2][0] * d, acc[i2][1] * d,
                                    acc[i2][2] * d, acc[i2][3] * d);
            *(float4*)&OutA[row * HID + tx * 4] = hn;   // Hn
            float4 a2 = make_float4(hn.x * d, hn.y * d, hn.z * d, hn.w * d);
            *(float4*)&OutB[row * HID + tx * 4] = a2;   // Acc (self term)
        }
    }
}

// ---------------- combined AB GEMM: AB = relu(Acc+b2) @ [Wm1_A | Wm1_B] -----
// 128 rows x 128 cols per block; microtile 8 rows x (4 A-cols + 4 B-cols).
__global__ void __launch_bounds__(256, 2)
k_gemm_ab(const float* __restrict__ X, const float* __restrict__ Wm1,
          const float* __restrict__ inb, float* __restrict__ AB) {
    __shared__ float sX[32][132];
    __shared__ float sWa[32][64];
    __shared__ float sWb[32][64];
    int t  = threadIdx.x;
    int br = blockIdx.x * 128;
    int tx = t & 15, ty = t >> 4;
    float acc[8][8] = {};

    for (int kc = 0; kc < HID; kc += 32) {
        #pragma unroll
        for (int i = 0; i < 4; i++) {
            int id = t + i * 256;
            int r  = id >> 3;
            int kb = (id & 7) * 4;
            int row = br + r;
            float4 v = make_float4(0.f, 0.f, 0.f, 0.f);
            if (row < NN) {
                v = *(const float4*)&X[row * HID + kc + kb];
                v.x = fmaxf(v.x + inb[kc + kb + 0], 0.f);
                v.y = fmaxf(v.y + inb[kc + kb + 1], 0.f);
                v.z = fmaxf(v.z + inb[kc + kb + 2], 0.f);
                v.w = fmaxf(v.w + inb[kc + kb + 3], 0.f);
            }
            sX[kb + 0][r] = v.x;
            sX[kb + 1][r] = v.y;
            sX[kb + 2][r] = v.z;
            sX[kb + 3][r] = v.w;
        }
        #pragma unroll
        for (int i = 0; i < 2; i++) {
            int id = t + i * 256;
            int kk = id >> 4, c4 = (id & 15) * 4;
            *(float4*)&sWa[kk][c4] = *(const float4*)&Wm1[(kc + kk) * 64 + c4];
            *(float4*)&sWb[kk][c4] = *(const float4*)&Wm1[(64 + kc + kk) * 64 + c4];
        }
        __syncthreads();
        #pragma unroll
        for (int kk = 0; kk < 32; kk++) {
            float a[8], b[8];
            *(float4*)&a[0] = *(const float4*)&sX[kk][ty * 8];
            *(float4*)&a[4] = *(const float4*)&sX[kk][ty * 8 + 4];
            *(float4*)&b[0] = *(const float4*)&sWa[kk][tx * 4];
            *(float4*)&b[4] = *(const float4*)&sWb[kk][tx * 4];
            #pragma unroll
            for (int i2 = 0; i2 < 8; i2++)
                #pragma unroll
                for (int j = 0; j < 8; j++)
                    acc[i2][j] += a[i2] * b[j];
        }
        __syncthreads();
    }
    #pragma unroll
    for (int i2 = 0; i2 < 8; i2++) {
        int row = br + ty * 8 + i2;
        if (row < NN) {
            *(float4*)&AB[row * 128 + tx * 4]      = *(float4*)&acc[i2][0];
            *(float4*)&AB[row * 128 + 64 + tx * 4] = *(float4*)&acc[i2][4];
        }
    }
}

// ---------------- edge scatter: Acc[dst] += Hn[src] * dinv[dst] -------------
// 8 threads per edge; each thread: 2 x (LDG.128 + v4 RED).
__global__ void k_scatter(const float* __restrict__ Hn, const int* __restrict__ deg,
                          const int* __restrict__ ei, float* __restrict__ Acc) {
    int tid = blockIdx.x * blockDim.x + threadIdx.x;
    if (tid >= NE * 8) return;
    int e = tid >> 3, q = tid & 7;
    int src = ei[e];
    int dst = ei[NE + e];
    float n = rsqrtf((float)deg[dst]);
    float4 v0 = *(const float4*)&Hn[src * HID + q * 8];
    float4 v1 = *(const float4*)&Hn[src * HID + q * 8 + 4];
    v0.x *= n; v0.y *= n; v0.z *= n; v0.w *= n;
    v1.x *= n; v1.y *= n; v1.z *= n; v1.w *= n;
    red_add_v4(&Acc[dst * HID + q * 8], v0);
    red_add_v4(&Acc[dst * HID + q * 8 + 4], v1);
}

// ---------------- edge MLP: half-warp per edge, 8 edges per half-warp -------
#define EMLP_BLOCKS 6250
__global__ void k_edge_mlp(const float* __restrict__ AB, const int* __restrict__ ei,
                           const float* __restrict__ attr, const float* __restrict__ Wm1,
                           const float* __restrict__ bm1, const float* __restrict__ Wm2,
                           const float* __restrict__ bm2, float* __restrict__ out) {
    __shared__ float sWe[EDIM][HID];   // Wm1 rows 128..143
    __shared__ float sW2[HID][2];
    __shared__ float sb1[HID];
    __shared__ float sb2[2];
    int t = threadIdx.x;
    const float* We = Wm1 + 128 * HID;
    for (int i = t; i < EDIM * HID; i += blockDim.x) ((float*)sWe)[i] = We[i];
    for (int i = t; i < HID * 2; i += blockDim.x)    ((float*)sW2)[i] = Wm2[i];
    if (t < HID) sb1[t] = bm1[t];
    if (t < 2)   sb2[t] = bm2[t];
    __syncthreads();

    const int HALVES = EMLP_BLOCKS * 256 / 16;       // 100000 half-warps
    int h = (blockIdx.x * blockDim.x + t) >> 4;
    int l = t & 15;

    #pragma unroll
    for (int it = 0; it < 8; it++) {
        int e = h + it * HALVES;
        if (e < NE) {
            int src = ei[e];
            int dst = ei[NE + e];
            float4 a = *(const float4*)&AB[src * 128 + l * 4];
            float4 b = *(const float4*)&AB[dst * 128 + 64 + l * 4];
            float av = attr[e * EDIM + l];

            float s0 = 0.f, s1 = 0.f, s2 = 0.f, s3 = 0.f;
            #pragma unroll
            for (int k = 0; k < EDIM; k++) {
                float ak = __shfl_sync(0xffffffffu, av, k, 16);
                s0 += ak * sWe[k][l * 4 + 0];
                s1 += ak * sWe[k][l * 4 + 1];
                s2 += ak * sWe[k][l * 4 + 2];
                s3 += ak * sWe[k][l * 4 + 3];
            }
            int c = l * 4;
            float e0 = fmaxf(a.x + b.x + s0 + sb1[c + 0], 0.f);
            float e1 = fmaxf(a.y + b.y + s1 + sb1[c + 1], 0.f);
            float e2 = fmaxf(a.z + b.z + s2 + sb1[c + 2], 0.f);
            float e3 = fmaxf(a.w + b.w + s3 + sb1[c + 3], 0.f);

            float p0 = e0 * sW2[c][0] + e1 * sW2[c + 1][0]
                     + e2 * sW2[c + 2][0] + e3 * sW2[c + 3][0];
            float p1 = e0 * sW2[c][1] + e1 * sW2[c + 1][1]
                     + e2 * sW2[c + 2][1] + e3 * sW2[c + 3][1];
            #pragma unroll
            for (int off = 8; off; off >>= 1) {
                p0 += __shfl_xor_sync(0xffffffffu, p0, off, 16);
                p1 += __shfl_xor_sync(0xffffffffu, p1, off, 16);
            }
            if (l == 0) {
                float2 r = make_float2(p0 + sb2[0], p1 + sb2[1]);
                *(float2*)&out[e * 2] = r;
            }
        }
    }
}

// ---------------- launch ----------------------------------------------------
extern "C" void kernel_launch(void* const* d_in, const int* in_sizes, int n_in,
                              void* d_out, int out_size) {
    const float* x    = (const float*)d_in[0];
    const int*   ei   = (const int*)d_in[1];
    const float* attr = (const float*)d_in[2];
    const float* W1   = (const float*)d_in[3];
    const float* b1   = (const float*)d_in[4];
    const float* W2   = (const float*)d_in[5];
    const float* b2   = (const float*)d_in[6];
    const float* Wm1  = (const float*)d_in[7];
    const float* bm1  = (const float*)d_in[8];
    const float* Wm2  = (const float*)d_in[9];
    const float* bm2  = (const float*)d_in[10];
    float* out = (float*)d_out;

    float *Hn, *Acc, *AB; int* deg;
    cudaGetSymbolAddress((void**)&Hn,  g_Hn);
    cudaGetSymbolAddress((void**)&Acc, g_Acc);
    cudaGetSymbolAddress((void**)&AB,  g_AB);
    cudaGetSymbolAddress((void**)&deg, g_deg);

    const int T = 256;
    int gb_nodes = (NN + T - 1) / T;
    int gb_edges = (NE + T - 1) / T;
    int gb_ev8   = (NE * 8 + T - 1) / T;
    int gb_gemm  = (NN + 127) / 128;

    // 1,2: degrees (dinv computed on the fly from deg everywhere)
    k_deg_init<<<gb_nodes, T>>>(deg);
    k_deg_count<<<gb_edges, T>>>(ei, deg);

    // 3: GCN layer 1 GEMM (Hn = (x@W1)*dinv, Acc = Hn*dinv)
    k_gemm<NDIM, false><<<gb_gemm, T>>>(x, W1, nullptr, deg, Hn, Acc);
    // 4: scatter (PROFILED LAUNCH)
    k_scatter<<<gb_ev8, T>>>(Hn, deg, ei, Acc);

    // 5,6: GCN layer 2
    k_gemm<HID, true><<<gb_gemm, T>>>(Acc, W2, b1, deg, Hn, Acc);
    k_scatter<<<gb_ev8, T>>>(Hn, deg, ei, Acc);

    // 7: combined edge-MLP partials A|B
    k_gemm_ab<<<gb_gemm, T>>>(Acc, Wm1, b2, AB);

    // 8: edge MLP
    k_edge_mlp<<<EMLP_BLOCKS, T>>>(AB, ei, attr, Wm1, bm1, Wm2, bm2, out);
}

// round 12
// speedup vs baseline: 1.1352x; 1.1352x over previous
#include <cuda_runtime.h>

#define NN 50000
#define NE 800000
#define NDIM 128
#define HID 64
#define EDIM 16

// ---------------- scratch (device globals; no allocation allowed) ----------
__device__ __align__(16) float g_Hn[NN * HID];     // (X@W) * dinv[row]
__device__ __align__(16) float g_Acc[NN * HID];    // aggregation accumulator
__device__ __align__(16) float g_AB[NN * 128];     // [A | B] per node for edge MLP
__device__ int g_deg[NN];

// ---------------- vector reduction helper ----------------------------------
__device__ __forceinline__ void red_add_v4(float* p, float4 v) {
    asm volatile("red.global.add.v4.f32 [%0], {%1,%2,%3,%4};"
                 :: "l"(p), "f"(v.x), "f"(v.y), "f"(v.z), "f"(v.w)
                 : "memory");
}

// ---------------- degree kernels -------------------------------------------
__global__ void k_deg_init(int* deg) {
    int i = blockIdx.x * blockDim.x + threadIdx.x;
    if (i < NN) deg[i] = 1;   // self-loop
}
__global__ void k_deg_count(const int* __restrict__ ei, int* deg) {
    int e = blockIdx.x * blockDim.x + threadIdx.x;
    if (e < NE) atomicAdd(&deg[ei[NE + e]], 1);
}

// ---------------- GEMM: Out = [relu(X+b)] @ W[K,64] ------------------------
// 128x64 tile, 256 threads, 8x4 microtile, K chunked by 32.
template <int K, bool IN_RELU>
__global__ void __launch_bounds__(256, 3)
k_gemm(const float* __restrict__ X, const float* __restrict__ W,
       const float* __restrict__ inb, const int* __restrict__ deg,
       float* __restrict__ OutA, float* __restrict__ OutB) {
    __shared__ float sX[32][132];   // [k][row], 16B-aligned stride
    __shared__ float sW[32][64];    // [k][col]
    int t  = threadIdx.x;
    int br = blockIdx.x * 128;
    int tx = t & 15, ty = t >> 4;
    float acc[8][4] = {};

    for (int kc = 0; kc < K; kc += 32) {
        #pragma unroll
        for (int i = 0; i < 4; i++) {
            int id = t + i * 256;
            int r  = id >> 3;
            int kb = (id & 7) * 4;
            int row = br + r;
            float4 v = make_float4(0.f, 0.f, 0.f, 0.f);
            if (row < NN) {
                v = *(const float4*)&X[row * K + kc + kb];
                if (IN_RELU) {
                    v.x = fmaxf(v.x + inb[kc + kb + 0], 0.f);
                    v.y = fmaxf(v.y + inb[kc + kb + 1], 0.f);
                    v.z = fmaxf(v.z + inb[kc + kb + 2], 0.f);
                    v.w = fmaxf(v.w + inb[kc + kb + 3], 0.f);
                }
            }
            sX[kb + 0][r] = v.x;
            sX[kb + 1][r] = v.y;
            sX[kb + 2][r] = v.z;
            sX[kb + 3][r] = v.w;
        }
        #pragma unroll
        for (int i = 0; i < 2; i++) {
            int id = t + i * 256;
            int kk = id >> 4, c4 = (id & 15) * 4;
            *(float4*)&sW[kk][c4] = *(const float4*)&W[(kc + kk) * 64 + c4];
        }
        __syncthreads();
        #pragma unroll
        for (int kk = 0; kk < 32; kk++) {
            float a[8], b[4];
            *(float4*)&a[0] = *(const float4*)&sX[kk][ty * 8];
            *(float4*)&a[4] = *(const float4*)&sX[kk][ty * 8 + 4];
            *(float4*)&b[0] = *(const float4*)&sW[kk][tx * 4];
            #pragma unroll
            for (int i2 = 0; i2 < 8; i2++)
                #pragma unroll
                for (int j = 0; j < 4; j++)
                    acc[i2][j] += a[i2] * b[j];
        }
        __syncthreads();
    }
    #pragma unroll
    for (int i2 = 0; i2 < 8; i2++) {
        int row = br + ty * 8 + i2;
        if (row < NN) {
            float d = rsqrtf((float)deg[row]);
            float4 hn = make_float4(acc[i2][0] * d, acc[i2][1] * d,
                                    acc[i2][2] * d, acc[i2][3] * d);
            *(float4*)&OutA[row * HID + tx * 4] = hn;   // Hn
            float4 a2 = make_float4(hn.x * d, hn.y * d, hn.z * d, hn.w * d);
            *(float4*)&OutB[row * HID + tx * 4] = a2;   // Acc (self term)
        }
    }
}

// ---------------- combined AB GEMM: AB = relu(Acc+b2) @ [Wm1_A | Wm1_B] -----
__global__ void __launch_bounds__(256, 2)
k_gemm_ab(const float* __restrict__ X, const float* __restrict__ Wm1,
          const float* __restrict__ inb, float* __restrict__ AB) {
    __shared__ float sX[32][132];
    __shared__ float sWa[32][64];
    __shared__ float sWb[32][64];
    int t  = threadIdx.x;
    int br = blockIdx.x * 128;
    int tx = t & 15, ty = t >> 4;
    float acc[8][8] = {};

    for (int kc = 0; kc < HID; kc += 32) {
        #pragma unroll
        for (int i = 0; i < 4; i++) {
            int id = t + i * 256;
            int r  = id >> 3;
            int kb = (id & 7) * 4;
            int row = br + r;
            float4 v = make_float4(0.f, 0.f, 0.f, 0.f);
            if (row < NN) {
                v = *(const float4*)&X[row * HID + kc + kb];
                v.x = fmaxf(v.x + inb[kc + kb + 0], 0.f);
                v.y = fmaxf(v.y + inb[kc + kb + 1], 0.f);
                v.z = fmaxf(v.z + inb[kc + kb + 2], 0.f);
                v.w = fmaxf(v.w + inb[kc + kb + 3], 0.f);
            }
            sX[kb + 0][r] = v.x;
            sX[kb + 1][r] = v.y;
            sX[kb + 2][r] = v.z;
            sX[kb + 3][r] = v.w;
        }
        #pragma unroll
        for (int i = 0; i < 2; i++) {
            int id = t + i * 256;
            int kk = id >> 4, c4 = (id & 15) * 4;
            *(float4*)&sWa[kk][c4] = *(const float4*)&Wm1[(kc + kk) * 64 + c4];
            *(float4*)&sWb[kk][c4] = *(const float4*)&Wm1[(64 + kc + kk) * 64 + c4];
        }
        __syncthreads();
        #pragma unroll
        for (int kk = 0; kk < 32; kk++) {
            float a[8], b[8];
            *(float4*)&a[0] = *(const float4*)&sX[kk][ty * 8];
            *(float4*)&a[4] = *(const float4*)&sX[kk][ty * 8 + 4];
            *(float4*)&b[0] = *(const float4*)&sWa[kk][tx * 4];
            *(float4*)&b[4] = *(const float4*)&sWb[kk][tx * 4];
            #pragma unroll
            for (int i2 = 0; i2 < 8; i2++)
                #pragma unroll
                for (int j = 0; j < 8; j++)
                    acc[i2][j] += a[i2] * b[j];
        }
        __syncthreads();
    }
    #pragma unroll
    for (int i2 = 0; i2 < 8; i2++) {
        int row = br + ty * 8 + i2;
        if (row < NN) {
            *(float4*)&AB[row * 128 + tx * 4]      = *(float4*)&acc[i2][0];
            *(float4*)&AB[row * 128 + 64 + tx * 4] = *(float4*)&acc[i2][4];
        }
    }
}

// ---------------- edge scatter: Acc[dst] += Hn[src] * dinv[dst] -------------
// 16 threads per edge; each thread: one independent LDG.128 + one v4 RED.
__global__ void k_scatter(const float* __restrict__ Hn, const int* __restrict__ deg,
                          const int* __restrict__ ei, float* __restrict__ Acc) {
    int tid = blockIdx.x * blockDim.x + threadIdx.x;
    if (tid >= NE * 16) return;
    int e = tid >> 4, q = tid & 15;
    int src = ei[e];
    int dst = ei[NE + e];
    float n = rsqrtf((float)deg[dst]);
    float4 v = *(const float4*)&Hn[src * HID + q * 4];
    v.x *= n; v.y *= n; v.z *= n; v.w *= n;
    red_add_v4(&Acc[dst * HID + q * 4], v);
}

// ---------------- edge MLP: half-warp per edge, 8 edges per half-warp -------
#define EMLP_BLOCKS 6250
__global__ void k_edge_mlp(const float* __restrict__ AB, const int* __restrict__ ei,
                           const float* __restrict__ attr, const float* __restrict__ Wm1,
                           const float* __restrict__ bm1, const float* __restrict__ Wm2,
                           const float* __restrict__ bm2, float* __restrict__ out) {
    __shared__ float sWe[EDIM][HID];   // Wm1 rows 128..143
    __shared__ float sW2[HID][2];
    __shared__ float sb1[HID];
    __shared__ float sb2[2];
    int t = threadIdx.x;
    const float* We = Wm1 + 128 * HID;
    for (int i = t; i < EDIM * HID; i += blockDim.x) ((float*)sWe)[i] = We[i];
    for (int i = t; i < HID * 2; i += blockDim.x)    ((float*)sW2)[i] = Wm2[i];
    if (t < HID) sb1[t] = bm1[t];
    if (t < 2)   sb2[t] = bm2[t];
    __syncthreads();

    const int HALVES = EMLP_BLOCKS * 256 / 16;       // 100000 half-warps
    int h = (blockIdx.x * blockDim.x + t) >> 4;
    int l = t & 15;

    #pragma unroll
    for (int it = 0; it < 8; it++) {
        int e = h + it * HALVES;
        if (e < NE) {
            int src = ei[e];
            int dst = ei[NE + e];
            float4 a = *(const float4*)&AB[src * 128 + l * 4];
            float4 b = *(const float4*)&AB[dst * 128 + 64 + l * 4];
            float av = attr[e * EDIM + l];

            float s0 = 0.f, s1 = 0.f, s2 = 0.f, s3 = 0.f;
            #pragma unroll
            for (int k = 0; k < EDIM; k++) {
                float ak = __shfl_sync(0xffffffffu, av, k, 16);
                s0 += ak * sWe[k][l * 4 + 0];
                s1 += ak * sWe[k][l * 4 + 1];
                s2 += ak * sWe[k][l * 4 + 2];
                s3 += ak * sWe[k][l * 4 + 3];
            }
            int c = l * 4;
            float e0 = fmaxf(a.x + b.x + s0 + sb1[c + 0], 0.f);
            float e1 = fmaxf(a.y + b.y + s1 + sb1[c + 1], 0.f);
            float e2 = fmaxf(a.z + b.z + s2 + sb1[c + 2], 0.f);
            float e3 = fmaxf(a.w + b.w + s3 + sb1[c + 3], 0.f);

            float p0 = e0 * sW2[c][0] + e1 * sW2[c + 1][0]
                     + e2 * sW2[c + 2][0] + e3 * sW2[c + 3][0];
            float p1 = e0 * sW2[c][1] + e1 * sW2[c + 1][1]
                     + e2 * sW2[c + 2][1] + e3 * sW2[c + 3][1];
            #pragma unroll
            for (int off = 8; off; off >>= 1) {
                p0 += __shfl_xor_sync(0xffffffffu, p0, off, 16);
                p1 += __shfl_xor_sync(0xffffffffu, p1, off, 16);
            }
            if (l == 0) {
                float2 r = make_float2(p0 + sb2[0], p1 + sb2[1]);
                *(float2*)&out[e * 2] = r;
            }
        }
    }
}

// ---------------- launch ----------------------------------------------------
extern "C" void kernel_launch(void* const* d_in, const int* in_sizes, int n_in,
                              void* d_out, int out_size) {
    const float* x    = (const float*)d_in[0];
    const int*   ei   = (const int*)d_in[1];
    const float* attr = (const float*)d_in[2];
    const float* W1   = (const float*)d_in[3];
    const float* b1   = (const float*)d_in[4];
    const float* W2   = (const float*)d_in[5];
    const float* b2   = (const float*)d_in[6];
    const float* Wm1  = (const float*)d_in[7];
    const float* bm1  = (const float*)d_in[8];
    const float* Wm2  = (const float*)d_in[9];
    const float* bm2  = (const float*)d_in[10];
    float* out = (float*)d_out;

    float *Hn, *Acc, *AB; int* deg;
    cudaGetSymbolAddress((void**)&Hn,  g_Hn);
    cudaGetSymbolAddress((void**)&Acc, g_Acc);
    cudaGetSymbolAddress((void**)&AB,  g_AB);
    cudaGetSymbolAddress((void**)&deg, g_deg);

    const int T = 256;
    int gb_nodes = (NN + T - 1) / T;
    int gb_edges = (NE + T - 1) / T;
    int gb_ev16  = (NE * 16 + T - 1) / T;
    int gb_gemm  = (NN + 127) / 128;

    // 1,2: degrees (dinv computed on the fly from deg everywhere)
    k_deg_init<<<gb_nodes, T>>>(deg);
    k_deg_count<<<gb_edges, T>>>(ei, deg);

    // 3: GCN layer 1 GEMM (Hn = (x@W1)*dinv, Acc = Hn*dinv)
    k_gemm<NDIM, false><<<gb_gemm, T>>>(x, W1, nullptr, deg, Hn, Acc);
    // 4: scatter (PROFILED LAUNCH)
    k_scatter<<<gb_ev16, T>>>(Hn, deg, ei, Acc);

    // 5,6: GCN layer 2
    k_gemm<HID, true><<<gb_gemm, T>>>(Acc, W2, b1, deg, Hn, Acc);
    k_scatter<<<gb_ev16, T>>>(Hn, deg, ei, Acc);

    // 7: combined edge-MLP partials A|B
    k_gemm_ab<<<gb_gemm, T>>>(Acc, Wm1, b2, AB);

    // 8: edge MLP
    k_edge_mlp<<<EMLP_BLOCKS, T>>>(AB, ei, attr, Wm1, bm1, Wm2, bm2, out);
}

// round 14
// speedup vs baseline: 1.1590x; 1.0210x over previous
#include <cuda_runtime.h>

#define NN 50000
#define NE 800000
#define NDIM 128
#define HID 64
#define EDIM 16

// ---------------- scratch (device globals; no allocation allowed) ----------
__device__ __align__(16) float g_Hn[NN * HID];     // (X@W) * dinv[row]
__device__ __align__(16) float g_Acc[NN * HID];    // aggregation accumulator
__device__ __align__(16) float g_AB[NN * 128];     // [A | B] per node for edge MLP
__device__ int   g_deg[NN];
__device__ float g_dinv[NN];

// ---------------- vector reduction helper ----------------------------------
__device__ __forceinline__ void red_add_v4(float* p, float4 v) {
    asm volatile("red.global.add.v4.f32 [%0], {%1,%2,%3,%4};"
                 :: "l"(p), "f"(v.x), "f"(v.y), "f"(v.z), "f"(v.w)
                 : "memory");
}

// ---------------- degree kernels -------------------------------------------
__global__ void k_deg_init(int* deg) {
    int i = blockIdx.x * blockDim.x + threadIdx.x;
    if (i < NN) deg[i] = 1;   // self-loop
}
__global__ void k_deg_count(const int* __restrict__ ei, int* deg) {
    int e = blockIdx.x * blockDim.x + threadIdx.x;
    if (e < NE) atomicAdd(&deg[ei[NE + e]], 1);
}
__global__ void k_deg_inv(const int* __restrict__ deg, float* dinv) {
    int i = blockIdx.x * blockDim.x + threadIdx.x;
    if (i < NN) dinv[i] = rsqrtf((float)deg[i]);
}

// ---------------- GEMM: Out = [relu(X+b)] @ W[K,64] ------------------------
// 128x64 tile, 256 threads, 8x4 microtile, K chunked by 32.
template <int K, bool IN_RELU>
__global__ void __launch_bounds__(256, 3)
k_gemm(const float* __restrict__ X, const float* __restrict__ W,
       const float* __restrict__ inb, const float* __restrict__ dinv,
       float* __restrict__ OutA, float* __restrict__ OutB) {
    __shared__ float sX[32][132];   // [k][row], 16B-aligned stride
    __shared__ float sW[32][64];    // [k][col]
    int t  = threadIdx.x;
    int br = blockIdx.x * 128;
    int tx = t & 15, ty = t >> 4;
    float acc[8][4] = {};

    for (int kc = 0; kc < K; kc += 32) {
        #pragma unroll
        for (int i = 0; i < 4; i++) {
            int id = t + i * 256;
            int r  = id >> 3;
            int kb = (id & 7) * 4;
            int row = br + r;
            float4 v = make_float4(0.f, 0.f, 0.f, 0.f);
            if (row < NN) {
                v = *(const float4*)&X[row * K + kc + kb];
                if (IN_RELU) {
                    v.x = fmaxf(v.x + inb[kc + kb + 0], 0.f);
                    v.y = fmaxf(v.y + inb[kc + kb + 1], 0.f);
                    v.z = fmaxf(v.z + inb[kc + kb + 2], 0.f);
                    v.w = fmaxf(v.w + inb[kc + kb + 3], 0.f);
                }
            }
            sX[kb + 0][r] = v.x;
            sX[kb + 1][r] = v.y;
            sX[kb + 2][r] = v.z;
            sX[kb + 3][r] = v.w;
        }
        #pragma unroll
        for (int i = 0; i < 2; i++) {
            int id = t + i * 256;
            int kk = id >> 4, c4 = (id & 15) * 4;
            *(float4*)&sW[kk][c4] = *(const float4*)&W[(kc + kk) * 64 + c4];
        }
        __syncthreads();
        #pragma unroll
        for (int kk = 0; kk < 32; kk++) {
            float a[8], b[4];
            *(float4*)&a[0] = *(const float4*)&sX[kk][ty * 8];
            *(float4*)&a[4] = *(const float4*)&sX[kk][ty * 8 + 4];
            *(float4*)&b[0] = *(const float4*)&sW[kk][tx * 4];
            #pragma unroll
            for (int i2 = 0; i2 < 8; i2++)
                #pragma unroll
                for (int j = 0; j < 4; j++)
                    acc[i2][j] += a[i2] * b[j];
        }
        __syncthreads();
    }
    #pragma unroll
    for (int i2 = 0; i2 < 8; i2++) {
        int row = br + ty * 8 + i2;
        if (row < NN) {
            float d = dinv[row];
            float4 hn = make_float4(acc[i2][0] * d, acc[i2][1] * d,
                                    acc[i2][2] * d, acc[i2][3] * d);
            *(float4*)&OutA[row * HID + tx * 4] = hn;   // Hn
            float4 a2 = make_float4(hn.x * d, hn.y * d, hn.z * d, hn.w * d);
            *(float4*)&OutB[row * HID + tx * 4] = a2;   // Acc (self term)
        }
    }
}

// ---------------- combined AB GEMM: AB = relu(Acc+b2) @ [Wm1_A | Wm1_B] -----
__global__ void __launch_bounds__(256, 2)
k_gemm_ab(const float* __restrict__ X, const float* __restrict__ Wm1,
          const float* __restrict__ inb, float* __restrict__ AB) {
    __shared__ float sX[32][132];
    __shared__ float sWa[32][64];
    __shared__ float sWb[32][64];
    int t  = threadIdx.x;
    int br = blockIdx.x * 128;
    int tx = t & 15, ty = t >> 4;
    float acc[8][8] = {};

    for (int kc = 0; kc < HID; kc += 32) {
        #pragma unroll
        for (int i = 0; i < 4; i++) {
            int id = t + i * 256;
            int r  = id >> 3;
            int kb = (id & 7) * 4;
            int row = br + r;
            float4 v = make_float4(0.f, 0.f, 0.f, 0.f);
            if (row < NN) {
                v = *(const float4*)&X[row * HID + kc + kb];
                v.x = fmaxf(v.x + inb[kc + kb + 0], 0.f);
                v.y = fmaxf(v.y + inb[kc + kb + 1], 0.f);
                v.z = fmaxf(v.z + inb[kc + kb + 2], 0.f);
                v.w = fmaxf(v.w + inb[kc + kb + 3], 0.f);
            }
            sX[kb + 0][r] = v.x;
            sX[kb + 1][r] = v.y;
            sX[kb + 2][r] = v.z;
            sX[kb + 3][r] = v.w;
        }
        #pragma unroll
        for (int i = 0; i < 2; i++) {
            int id = t + i * 256;
            int kk = id >> 4, c4 = (id & 15) * 4;
            *(float4*)&sWa[kk][c4] = *(const float4*)&Wm1[(kc + kk) * 64 + c4];
            *(float4*)&sWb[kk][c4] = *(const float4*)&Wm1[(64 + kc + kk) * 64 + c4];
        }
        __syncthreads();
        #pragma unroll
        for (int kk = 0; kk < 32; kk++) {
            float a[8], b[8];
            *(float4*)&a[0] = *(const float4*)&sX[kk][ty * 8];
            *(float4*)&a[4] = *(const float4*)&sX[kk][ty * 8 + 4];
            *(float4*)&b[0] = *(const float4*)&sWa[kk][tx * 4];
            *(float4*)&b[4] = *(const float4*)&sWb[kk][tx * 4];
            #pragma unroll
            for (int i2 = 0; i2 < 8; i2++)
                #pragma unroll
                for (int j = 0; j < 8; j++)
                    acc[i2][j] += a[i2] * b[j];
        }
        __syncthreads();
    }
    #pragma unroll
    for (int i2 = 0; i2 < 8; i2++) {
        int row = br + ty * 8 + i2;
        if (row < NN) {
            *(float4*)&AB[row * 128 + tx * 4]      = *(float4*)&acc[i2][0];
            *(float4*)&AB[row * 128 + 64 + tx * 4] = *(float4*)&acc[i2][4];
        }
    }
}

// ---------------- edge scatter: Acc[dst] += Hn[src] * dinv[dst] -------------
// 16 threads per edge; each thread: one independent LDG.128 + one v4 RED.
__global__ void k_scatter(const float* __restrict__ Hn, const float* __restrict__ dinv,
                          const int* __restrict__ ei, float* __restrict__ Acc) {
    int tid = blockIdx.x * blockDim.x + threadIdx.x;
    if (tid >= NE * 16) return;
    int e = tid >> 4, q = tid & 15;
    int src = ei[e];
    int dst = ei[NE + e];
    float n = dinv[dst];
    float4 v = *(const float4*)&Hn[src * HID + q * 4];
    v.x *= n; v.y *= n; v.z *= n; v.w *= n;
    red_add_v4(&Acc[dst * HID + q * 4], v);
}

// ---------------- edge MLP: half-warp per edge, 8 edges per half-warp -------
// Vectorized smem: sWe4[k][g] = We[k][4g..4g+3]; w2c0/w2c1 pack Wm2 columns.
#define EMLP_BLOCKS 6250
__global__ void k_edge_mlp(const float* __restrict__ AB, const int* __restrict__ ei,
                           const float* __restrict__ attr, const float* __restrict__ Wm1,
                           const float* __restrict__ bm1, const float* __restrict__ Wm2,
                           const float* __restrict__ bm2, float* __restrict__ out) {
    __shared__ float4 sWe4[EDIM][16];  // [k][col-group]
    __shared__ float4 w2c0[16];        // (Wm2[4g..4g+3][0])
    __shared__ float4 w2c1[16];        // (Wm2[4g..4g+3][1])
    __shared__ float4 sb1v[16];        // bm1 groups
    __shared__ float  sb2[2];
    int t = threadIdx.x;
    const float* We = Wm1 + 128 * HID;
    for (int i = t; i < EDIM * 16; i += blockDim.x) {
        int k = i >> 4, g = i & 15;
        sWe4[k][g] = *(const float4*)&We[k * HID + g * 4];
    }
    if (t < 16) {
        int g = t;
        w2c0[g] = make_float4(Wm2[(4*g+0)*2], Wm2[(4*g+1)*2], Wm2[(4*g+2)*2], Wm2[(4*g+3)*2]);
        w2c1[g] = make_float4(Wm2[(4*g+0)*2+1], Wm2[(4*g+1)*2+1], Wm2[(4*g+2)*2+1], Wm2[(4*g+3)*2+1]);
        sb1v[g] = *(const float4*)&bm1[g * 4];
    }
    if (t < 2) sb2[t] = bm2[t];
    __syncthreads();

    const int HALVES = EMLP_BLOCKS * 256 / 16;       // 100000 half-warps
    int h = (blockIdx.x * blockDim.x + t) >> 4;
    int l = t & 15;

    #pragma unroll
    for (int it = 0; it < 8; it++) {
        int e = h + it * HALVES;
        if (e < NE) {
            int src = ei[e];
            int dst = ei[NE + e];
            float4 a = *(const float4*)&AB[src * 128 + l * 4];
            float4 b = *(const float4*)&AB[dst * 128 + 64 + l * 4];
            float av = attr[e * EDIM + l];

            float4 s = make_float4(0.f, 0.f, 0.f, 0.f);
            #pragma unroll
            for (int k = 0; k < EDIM; k++) {
                float ak = __shfl_sync(0xffffffffu, av, k, 16);
                float4 w = sWe4[k][l];
                s.x += ak * w.x;
                s.y += ak * w.y;
                s.z += ak * w.z;
                s.w += ak * w.w;
            }
            float4 bias = sb1v[l];
            float e0 = fmaxf(a.x + b.x + s.x + bias.x, 0.f);
            float e1 = fmaxf(a.y + b.y + s.y + bias.y, 0.f);
            float e2 = fmaxf(a.z + b.z + s.z + bias.z, 0.f);
            float e3 = fmaxf(a.w + b.w + s.w + bias.w, 0.f);

            float4 wc0 = w2c0[l];
            float4 wc1 = w2c1[l];
            float p0 = e0 * wc0.x + e1 * wc0.y + e2 * wc0.z + e3 * wc0.w;
            float p1 = e0 * wc1.x + e1 * wc1.y + e2 * wc1.z + e3 * wc1.w;
            #pragma unroll
            for (int off = 8; off; off >>= 1) {
                p0 += __shfl_xor_sync(0xffffffffu, p0, off, 16);
                p1 += __shfl_xor_sync(0xffffffffu, p1, off, 16);
            }
            if (l == 0) {
                float2 r = make_float2(p0 + sb2[0], p1 + sb2[1]);
                *(float2*)&out[e * 2] = r;
            }
        }
    }
}

// ---------------- launch ----------------------------------------------------
extern "C" void kernel_launch(void* const* d_in, const int* in_sizes, int n_in,
                              void* d_out, int out_size) {
    const float* x    = (const float*)d_in[0];
    const int*   ei   = (const int*)d_in[1];
    const float* attr = (const float*)d_in[2];
    const float* W1   = (const float*)d_in[3];
    const float* b1   = (const float*)d_in[4];
    const float* W2   = (const float*)d_in[5];
    const float* b2   = (const float*)d_in[6];
    const float* Wm1  = (const float*)d_in[7];
    const float* bm1  = (const float*)d_in[8];
    const float* Wm2  = (const float*)d_in[9];
    const float* bm2  = (const float*)d_in[10];
    float* out = (float*)d_out;

    float *Hn, *Acc, *AB, *dinv; int* deg;
    cudaGetSymbolAddress((void**)&Hn,   g_Hn);
    cudaGetSymbolAddress((void**)&Acc,  g_Acc);
    cudaGetSymbolAddress((void**)&AB,   g_AB);
    cudaGetSymbolAddress((void**)&deg,  g_deg);
    cudaGetSymbolAddress((void**)&dinv, g_dinv);

    const int T = 256;
    int gb_nodes = (NN + T - 1) / T;
    int gb_edges = (NE + T - 1) / T;
    int gb_ev16  = (NE * 16 + T - 1) / T;
    int gb_gemm  = (NN + 127) / 128;

    // 1-3: degrees + dinv
    k_deg_init<<<gb_nodes, T>>>(deg);
    k_deg_count<<<gb_edges, T>>>(ei, deg);
    k_deg_inv<<<gb_nodes, T>>>(deg, dinv);

    // 4: GCN layer 1 GEMM (PROFILED LAUNCH)
    k_gemm<NDIM, false><<<gb_gemm, T>>>(x, W1, nullptr, dinv, Hn, Acc);
    k_scatter<<<gb_ev16, T>>>(Hn, dinv, ei, Acc);

    // GCN layer 2
    k_gemm<HID, true><<<gb_gemm, T>>>(Acc, W2, b1, dinv, Hn, Acc);
    k_scatter<<<gb_ev16, T>>>(Hn, dinv, ei, Acc);

    // combined edge-MLP partials A|B
    k_gemm_ab<<<gb_gemm, T>>>(Acc, Wm1, b2, AB);

    // edge MLP
    k_edge_mlp<<<EMLP_BLOCKS, T>>>(AB, ei, attr, Wm1, bm1, Wm2, bm2, out);
}

// round 15
// speedup vs baseline: 1.5842x; 1.3669x over previous
#include <cuda_runtime.h>

#define NN 50000
#define NE 800000
#define NDIM 128
#define HID 64
#define EDIM 16

// ---------------- scratch (device globals; no allocation allowed) ----------
__device__ __align__(16) float g_Hn[NN * HID];     // (X@W) * dinv[row]
__device__ __align__(16) float g_Acc[NN * HID];    // aggregation accumulator
__device__ __align__(16) float g_AB[NN * 128];     // [A | B] per node for edge MLP
__device__ int   g_deg[NN];
__device__ float g_dinv[NN];

// ---------------- vector reduction helper ----------------------------------
__device__ __forceinline__ void red_add_v4(float* p, float4 v) {
    asm volatile("red.global.add.v4.f32 [%0], {%1,%2,%3,%4};"
                 :: "l"(p), "f"(v.x), "f"(v.y), "f"(v.z), "f"(v.w)
                 : "memory");
}

// ---------------- degree kernels -------------------------------------------
__global__ void k_deg_init(int* deg) {
    int i = blockIdx.x * blockDim.x + threadIdx.x;
    if (i < NN) deg[i] = 1;   // self-loop
}
__global__ void k_deg_count(const int* __restrict__ ei, int* deg) {
    int e = blockIdx.x * blockDim.x + threadIdx.x;
    if (e < NE) atomicAdd(&deg[ei[NE + e]], 1);
}
__global__ void k_deg_inv(const int* __restrict__ deg, float* dinv) {
    int i = blockIdx.x * blockDim.x + threadIdx.x;
    if (i < NN) dinv[i] = rsqrtf((float)deg[i]);
}

// ---------------- GEMM: Out = [relu(X+b)] @ W[K,64] ------------------------
// 128x64 tile, 256 threads, 8x4 microtile, K chunked by 32.
template <int K, bool IN_RELU>
__global__ void __launch_bounds__(256, 3)
k_gemm(const float* __restrict__ X, const float* __restrict__ W,
       const float* __restrict__ inb, const float* __restrict__ dinv,
       float* __restrict__ OutA, float* __restrict__ OutB) {
    __shared__ float sX[32][132];   // [k][row], 16B-aligned stride
    __shared__ float sW[32][64];    // [k][col]
    int t  = threadIdx.x;
    int br = blockIdx.x * 128;
    int tx = t & 15, ty = t >> 4;
    float acc[8][4] = {};

    for (int kc = 0; kc < K; kc += 32) {
        #pragma unroll
        for (int i = 0; i < 4; i++) {
            int id = t + i * 256;
            int r  = id >> 3;
            int kb = (id & 7) * 4;
            int row = br + r;
            float4 v = make_float4(0.f, 0.f, 0.f, 0.f);
            if (row < NN) {
                v = *(const float4*)&X[row * K + kc + kb];
                if (IN_RELU) {
                    v.x = fmaxf(v.x + inb[kc + kb + 0], 0.f);
                    v.y = fmaxf(v.y + inb[kc + kb + 1], 0.f);
                    v.z = fmaxf(v.z + inb[kc + kb + 2], 0.f);
                    v.w = fmaxf(v.w + inb[kc + kb + 3], 0.f);
                }
            }
            sX[kb + 0][r] = v.x;
            sX[kb + 1][r] = v.y;
            sX[kb + 2][r] = v.z;
            sX[kb + 3][r] = v.w;
        }
        #pragma unroll
        for (int i = 0; i < 2; i++) {
            int id = t + i * 256;
            int kk = id >> 4, c4 = (id & 15) * 4;
            *(float4*)&sW[kk][c4] = *(const float4*)&W[(kc + kk) * 64 + c4];
        }
        __syncthreads();
        #pragma unroll
        for (int kk = 0; kk < 32; kk++) {
            float a[8], b[4];
            *(float4*)&a[0] = *(const float4*)&sX[kk][ty * 8];
            *(float4*)&a[4] = *(const float4*)&sX[kk][ty * 8 + 4];
            *(float4*)&b[0] = *(const float4*)&sW[kk][tx * 4];
            #pragma unroll
            for (int i2 = 0; i2 < 8; i2++)
                #pragma unroll
                for (int j = 0; j < 4; j++)
                    acc[i2][j] += a[i2] * b[j];
        }
        __syncthreads();
    }
    #pragma unroll
    for (int i2 = 0; i2 < 8; i2++) {
        int row = br + ty * 8 + i2;
        if (row < NN) {
            float d = dinv[row];
            float4 hn = make_float4(acc[i2][0] * d, acc[i2][1] * d,
                                    acc[i2][2] * d, acc[i2][3] * d);
            *(float4*)&OutA[row * HID + tx * 4] = hn;   // Hn
            float4 a2 = make_float4(hn.x * d, hn.y * d, hn.z * d, hn.w * d);
            *(float4*)&OutB[row * HID + tx * 4] = a2;   // Acc (self term)
        }
    }
}

// ---------------- combined AB GEMM: AB = relu(Acc+b2) @ [Wm1_A | Wm1_B] -----
__global__ void __launch_bounds__(256, 2)
k_gemm_ab(const float* __restrict__ X, const float* __restrict__ Wm1,
          const float* __restrict__ inb, float* __restrict__ AB) {
    __shared__ float sX[32][132];
    __shared__ float sWa[32][64];
    __shared__ float sWb[32][64];
    int t  = threadIdx.x;
    int br = blockIdx.x * 128;
    int tx = t & 15, ty = t >> 4;
    float acc[8][8] = {};

    for (int kc = 0; kc < HID; kc += 32) {
        #pragma unroll
        for (int i = 0; i < 4; i++) {
            int id = t + i * 256;
            int r  = id >> 3;
            int kb = (id & 7) * 4;
            int row = br + r;
            float4 v = make_float4(0.f, 0.f, 0.f, 0.f);
            if (row < NN) {
                v = *(const float4*)&X[row * HID + kc + kb];
                v.x = fmaxf(v.x + inb[kc + kb + 0], 0.f);
                v.y = fmaxf(v.y + inb[kc + kb + 1], 0.f);
                v.z = fmaxf(v.z + inb[kc + kb + 2], 0.f);
                v.w = fmaxf(v.w + inb[kc + kb + 3], 0.f);
            }
            sX[kb + 0][r] = v.x;
            sX[kb + 1][r] = v.y;
            sX[kb + 2][r] = v.z;
            sX[kb + 3][r] = v.w;
        }
        #pragma unroll
        for (int i = 0; i < 2; i++) {
            int id = t + i * 256;
            int kk = id >> 4, c4 = (id & 15) * 4;
            *(float4*)&sWa[kk][c4] = *(const float4*)&Wm1[(kc + kk) * 64 + c4];
            *(float4*)&sWb[kk][c4] = *(const float4*)&Wm1[(64 + kc + kk) * 64 + c4];
        }
        __syncthreads();
        #pragma unroll
        for (int kk = 0; kk < 32; kk++) {
            float a[8], b[8];
            *(float4*)&a[0] = *(const float4*)&sX[kk][ty * 8];
            *(float4*)&a[4] = *(const float4*)&sX[kk][ty * 8 + 4];
            *(float4*)&b[0] = *(const float4*)&sWa[kk][tx * 4];
            *(float4*)&b[4] = *(const float4*)&sWb[kk][tx * 4];
            #pragma unroll
            for (int i2 = 0; i2 < 8; i2++)
                #pragma unroll
                for (int j = 0; j < 8; j++)
                    acc[i2][j] += a[i2] * b[j];
        }
        __syncthreads();
    }
    #pragma unroll
    for (int i2 = 0; i2 < 8; i2++) {
        int row = br + ty * 8 + i2;
        if (row < NN) {
            *(float4*)&AB[row * 128 + tx * 4]      = *(float4*)&acc[i2][0];
            *(float4*)&AB[row * 128 + 64 + tx * 4] = *(float4*)&acc[i2][4];
        }
    }
}

// ---------------- edge scatter: Acc[dst] += Hn[src] * dinv[dst] -------------
// 16 threads per edge; each thread: one independent LDG.128 + one v4 RED.
__global__ void k_scatter(const float* __restrict__ Hn, const float* __restrict__ dinv,
                          const int* __restrict__ ei, float* __restrict__ Acc) {
    int tid = blockIdx.x * blockDim.x + threadIdx.x;
    if (tid >= NE * 16) return;
    int e = tid >> 4, q = tid & 15;
    int src = ei[e];
    int dst = ei[NE + e];
    float n = dinv[dst];
    float4 v = *(const float4*)&Hn[src * HID + q * 4];
    v.x *= n; v.y *= n; v.z *= n; v.w *= n;
    red_add_v4(&Acc[dst * HID + q * 4], v);
}

// ---------------- fused edge kernel: GEMM-structured -------------------------
// Block = 128 edges, 256 threads. Microtile: 8 edges x 4 hidden-cols.
// z[e][c] = attr[e]@We[:,c] + A[src][c] + B[dst][c] + bm1[c];
// out[e] = relu(z[e]) @ Wm2 + bm2.
#define EB 128
__global__ void __launch_bounds__(256)
k_edge_fused(const float* __restrict__ AB, const int* __restrict__ ei,
             const float* __restrict__ attr, const float* __restrict__ Wm1,
             const float* __restrict__ bm1, const float* __restrict__ Wm2,
             const float* __restrict__ bm2, float* __restrict__ out) {
    __shared__ float  sAt[EDIM][132];   // attr^T: [k][edge]
    __shared__ float  sWe[EDIM][64];    // Wm1 rows 128..143
    __shared__ int    ssrc[EB], sdst[EB];
    __shared__ float4 w2c0s[16], w2c1s[16], sb1v[16];
    __shared__ float  sb2[2];

    int t  = threadIdx.x;
    int E0 = blockIdx.x * EB;

    // stage attr (128 edges x 16) transposed; 2 x LDG.128 per thread
    {
        const float4* ap = (const float4*)(attr + (long)E0 * EDIM);
        #pragma unroll
        for (int j = 0; j < 2; j++) {
            float4 v = ap[t * 2 + j];
            int fidx = t * 8 + j * 4;
            int e = fidx >> 4, k = fidx & 15;
            sAt[k + 0][e] = v.x;
            sAt[k + 1][e] = v.y;
            sAt[k + 2][e] = v.z;
            sAt[k + 3][e] = v.w;
        }
    }
    // stage We (16 x 64): 1 float4 per thread
    {
        int kk = t >> 4, c4 = (t & 15) * 4;
        *(float4*)&sWe[kk][c4] = *(const float4*)&Wm1[(128 + kk) * HID + c4];
    }
    // stage edge indices
    if (t < EB) ssrc[t] = ei[E0 + t];
    else        sdst[t - EB] = ei[NE + E0 + (t - EB)];
    // stage small tables
    if (t < 16) {
        int g = t;
        w2c0s[g] = make_float4(Wm2[(4*g+0)*2],   Wm2[(4*g+1)*2],
                               Wm2[(4*g+2)*2],   Wm2[(4*g+3)*2]);
        w2c1s[g] = make_float4(Wm2[(4*g+0)*2+1], Wm2[(4*g+1)*2+1],
                               Wm2[(4*g+2)*2+1], Wm2[(4*g+3)*2+1]);
        sb1v[g]  = *(const float4*)&bm1[g * 4];
    }
    if (t < 2) sb2[t] = bm2[t];
    __syncthreads();

    int tx = t & 15, ty = t >> 4;

    // attr @ We  (K=16 dense GEMM): acc[8 edges][4 cols]
    float acc[8][4] = {};
    #pragma unroll
    for (int kk = 0; kk < EDIM; kk++) {
        float a[8], b[4];
        *(float4*)&a[0] = *(const float4*)&sAt[kk][ty * 8];
        *(float4*)&a[4] = *(const float4*)&sAt[kk][ty * 8 + 4];
        *(float4*)&b[0] = *(const float4*)&sWe[kk][tx * 4];
        #pragma unroll
        for (int i = 0; i < 8; i++)
            #pragma unroll
            for (int j = 0; j < 4; j++)
                acc[i][j] += a[i] * b[j];
    }

    float4 bias = sb1v[tx];
    float4 wc0  = w2c0s[tx];
    float4 wc1  = w2c1s[tx];
    float  b2x  = sb2[0], b2y = sb2[1];

    // epilogue: 2 edges per iteration, 4 independent gathers batched
    #pragma unroll
    for (int i = 0; i < 8; i += 2) {
        int le0 = ty * 8 + i, le1 = le0 + 1;
        int s0 = ssrc[le0], d0 = sdst[le0];
        int s1 = ssrc[le1], d1 = sdst[le1];
        float4 A0 = *(const float4*)&AB[s0 * 128 + tx * 4];
        float4 B0 = *(const float4*)&AB[d0 * 128 + 64 + tx * 4];
        float4 A1 = *(const float4*)&AB[s1 * 128 + tx * 4];
        float4 B1 = *(const float4*)&AB[d1 * 128 + 64 + tx * 4];

        float z00 = fmaxf(acc[i][0] + A0.x + B0.x + bias.x, 0.f);
        float z01 = fmaxf(acc[i][1] + A0.y + B0.y + bias.y, 0.f);
        float z02 = fmaxf(acc[i][2] + A0.z + B0.z + bias.z, 0.f);
        float z03 = fmaxf(acc[i][3] + A0.w + B0.w + bias.w, 0.f);
        float p0 = z00 * wc0.x + z01 * wc0.y + z02 * wc0.z + z03 * wc0.w;
        float p1 = z00 * wc1.x + z01 * wc1.y + z02 * wc1.z + z03 * wc1.w;

        float z10 = fmaxf(acc[i+1][0] + A1.x + B1.x + bias.x, 0.f);
        float z11 = fmaxf(acc[i+1][1] + A1.y + B1.y + bias.y, 0.f);
        float z12 = fmaxf(acc[i+1][2] + A1.z + B1.z + bias.z, 0.f);
        float z13 = fmaxf(acc[i+1][3] + A1.w + B1.w + bias.w, 0.f);
        float q0 = z10 * wc0.x + z11 * wc0.y + z12 * wc0.z + z13 * wc0.w;
        float q1 = z10 * wc1.x + z11 * wc1.y + z12 * wc1.z + z13 * wc1.w;

        #pragma unroll
        for (int off = 8; off; off >>= 1) {
            p0 += __shfl_xor_sync(0xffffffffu, p0, off, 16);
            p1 += __shfl_xor_sync(0xffffffffu, p1, off, 16);
            q0 += __shfl_xor_sync(0xffffffffu, q0, off, 16);
            q1 += __shfl_xor_sync(0xffffffffu, q1, off, 16);
        }
        if (tx == 0) {
            *(float2*)&out[(E0 + le0) * 2] = make_float2(p0 + b2x, p1 + b2y);
            *(float2*)&out[(E0 + le1) * 2] = make_float2(q0 + b2x, q1 + b2y);
        }
    }
}

// ---------------- launch ----------------------------------------------------
extern "C" void kernel_launch(void* const* d_in, const int* in_sizes, int n_in,
                              void* d_out, int out_size) {
    const float* x    = (const float*)d_in[0];
    const int*   ei   = (const int*)d_in[1];
    const float* attr = (const float*)d_in[2];
    const float* W1   = (const float*)d_in[3];
    const float* b1   = (const float*)d_in[4];
    const float* W2   = (const float*)d_in[5];
    const float* b2   = (const float*)d_in[6];
    const float* Wm1  = (const float*)d_in[7];
    const float* bm1  = (const float*)d_in[8];
    const float* Wm2  = (const float*)d_in[9];
    const float* bm2  = (const float*)d_in[10];
    float* out = (float*)d_out;

    float *Hn, *Acc, *AB, *dinv; int* deg;
    cudaGetSymbolAddress((void**)&Hn,   g_Hn);
    cudaGetSymbolAddress((void**)&Acc,  g_Acc);
    cudaGetSymbolAddress((void**)&AB,   g_AB);
    cudaGetSymbolAddress((void**)&deg,  g_deg);
    cudaGetSymbolAddress((void**)&dinv, g_dinv);

    const int T = 256;
    int gb_nodes = (NN + T - 1) / T;
    int gb_edges = (NE + T - 1) / T;
    int gb_ev16  = (NE * 16 + T - 1) / T;
    int gb_gemm  = (NN + 127) / 128;
    int gb_edge  = NE / EB;   // 6250, exact

    // 1-3: degrees + dinv
    k_deg_init<<<gb_nodes, T>>>(deg);
    k_deg_count<<<gb_edges, T>>>(ei, deg);
    k_deg_inv<<<gb_nodes, T>>>(deg, dinv);

    // 4: GCN layer 1 GEMM (PROFILED LAUNCH)
    k_gemm<NDIM, false><<<gb_gemm, T>>>(x, W1, nullptr, dinv, Hn, Acc);
    k_scatter<<<gb_ev16, T>>>(Hn, dinv, ei, Acc);

    // GCN layer 2
    k_gemm<HID, true><<<gb_gemm, T>>>(Acc, W2, b1, dinv, Hn, Acc);
    k_scatter<<<gb_ev16, T>>>(Hn, dinv, ei, Acc);

    // combined edge-MLP partials A|B
    k_gemm_ab<<<gb_gemm, T>>>(Acc, Wm1, b2, AB);

    // fused edge MLP (GEMM-structured)
    k_edge_fused<<<gb_edge, T>>>(AB, ei, attr, Wm1, bm1, Wm2, bm2, out);
}

// round 16
// speedup vs baseline: 1.6185x; 1.0216x over previous
#include <cuda_runtime.h>

#define NN 50000
#define NE 800000
#define NDIM 128
#define HID 64
#define EDIM 16

// ---------------- scratch (device globals; no allocation allowed) ----------
__device__ __align__(16) float g_Hn[NN * HID];     // (X@W) * dinv[row]
__device__ __align__(16) float g_Acc[NN * HID];    // aggregation accumulator
__device__ __align__(16) float g_AB[NN * 128];     // [A | B] per node for edge MLP
__device__ int   g_deg[NN];
__device__ float g_dinv[NN];

// ---------------- vector reduction helper ----------------------------------
__device__ __forceinline__ void red_add_v4(float* p, float4 v) {
    asm volatile("red.global.add.v4.f32 [%0], {%1,%2,%3,%4};"
                 :: "l"(p), "f"(v.x), "f"(v.y), "f"(v.z), "f"(v.w)
                 : "memory");
}

// ---------------- degree kernels -------------------------------------------
__global__ void k_deg_init(int* deg) {
    int i = blockIdx.x * blockDim.x + threadIdx.x;
    if (i < NN) deg[i] = 1;   // self-loop
}
__global__ void k_deg_count(const int* __restrict__ ei, int* deg) {
    int e = blockIdx.x * blockDim.x + threadIdx.x;
    if (e < NE) atomicAdd(&deg[ei[NE + e]], 1);
}
__global__ void k_deg_inv(const int* __restrict__ deg, float* dinv) {
    int i = blockIdx.x * blockDim.x + threadIdx.x;
    if (i < NN) dinv[i] = rsqrtf((float)deg[i]);
}

// ---------------- GEMM: Out = [relu(X+b)] @ W[K,64] ------------------------
// 128x64 tile, 256 threads, 8x4 microtile, K chunked by 32.
template <int K, bool IN_RELU>
__global__ void __launch_bounds__(256, 3)
k_gemm(const float* __restrict__ X, const float* __restrict__ W,
       const float* __restrict__ inb, const float* __restrict__ dinv,
       float* __restrict__ OutA, float* __restrict__ OutB) {
    __shared__ float sX[32][132];   // [k][row], 16B-aligned stride
    __shared__ float sW[32][64];    // [k][col]
    int t  = threadIdx.x;
    int br = blockIdx.x * 128;
    int tx = t & 15, ty = t >> 4;
    float acc[8][4] = {};

    for (int kc = 0; kc < K; kc += 32) {
        #pragma unroll
        for (int i = 0; i < 4; i++) {
            int id = t + i * 256;
            int r  = id >> 3;
            int kb = (id & 7) * 4;
            int row = br + r;
            float4 v = make_float4(0.f, 0.f, 0.f, 0.f);
            if (row < NN) {
                v = *(const float4*)&X[row * K + kc + kb];
                if (IN_RELU) {
                    v.x = fmaxf(v.x + inb[kc + kb + 0], 0.f);
                    v.y = fmaxf(v.y + inb[kc + kb + 1], 0.f);
                    v.z = fmaxf(v.z + inb[kc + kb + 2], 0.f);
                    v.w = fmaxf(v.w + inb[kc + kb + 3], 0.f);
                }
            }
            sX[kb + 0][r] = v.x;
            sX[kb + 1][r] = v.y;
            sX[kb + 2][r] = v.z;
            sX[kb + 3][r] = v.w;
        }
        #pragma unroll
        for (int i = 0; i < 2; i++) {
            int id = t + i * 256;
            int kk = id >> 4, c4 = (id & 15) * 4;
            *(float4*)&sW[kk][c4] = *(const float4*)&W[(kc + kk) * 64 + c4];
        }
        __syncthreads();
        #pragma unroll
        for (int kk = 0; kk < 32; kk++) {
            float a[8], b[4];
            *(float4*)&a[0] = *(const float4*)&sX[kk][ty * 8];
            *(float4*)&a[4] = *(const float4*)&sX[kk][ty * 8 + 4];
            *(float4*)&b[0] = *(const float4*)&sW[kk][tx * 4];
            #pragma unroll
            for (int i2 = 0; i2 < 8; i2++)
                #pragma unroll
                for (int j = 0; j < 4; j++)
                    acc[i2][j] += a[i2] * b[j];
        }
        __syncthreads();
    }
    #pragma unroll
    for (int i2 = 0; i2 < 8; i2++) {
        int row = br + ty * 8 + i2;
        if (row < NN) {
            float d = dinv[row];
            float4 hn = make_float4(acc[i2][0] * d, acc[i2][1] * d,
                                    acc[i2][2] * d, acc[i2][3] * d);
            *(float4*)&OutA[row * HID + tx * 4] = hn;   // Hn
            float4 a2 = make_float4(hn.x * d, hn.y * d, hn.z * d, hn.w * d);
            *(float4*)&OutB[row * HID + tx * 4] = a2;   // Acc (self term)
        }
    }
}

// ---------------- combined AB GEMM: AB = relu(Acc+b2) @ [Wm1_A | Wm1_B] -----
__global__ void __launch_bounds__(256, 2)
k_gemm_ab(const float* __restrict__ X, const float* __restrict__ Wm1,
          const float* __restrict__ inb, float* __restrict__ AB) {
    __shared__ float sX[32][132];
    __shared__ float sWa[32][64];
    __shared__ float sWb[32][64];
    int t  = threadIdx.x;
    int br = blockIdx.x * 128;
    int tx = t & 15, ty = t >> 4;
    float acc[8][8] = {};

    for (int kc = 0; kc < HID; kc += 32) {
        #pragma unroll
        for (int i = 0; i < 4; i++) {
            int id = t + i * 256;
            int r  = id >> 3;
            int kb = (id & 7) * 4;
            int row = br + r;
            float4 v = make_float4(0.f, 0.f, 0.f, 0.f);
            if (row < NN) {
                v = *(const float4*)&X[row * HID + kc + kb];
                v.x = fmaxf(v.x + inb[kc + kb + 0], 0.f);
                v.y = fmaxf(v.y + inb[kc + kb + 1], 0.f);
                v.z = fmaxf(v.z + inb[kc + kb + 2], 0.f);
                v.w = fmaxf(v.w + inb[kc + kb + 3], 0.f);
            }
            sX[kb + 0][r] = v.x;
            sX[kb + 1][r] = v.y;
            sX[kb + 2][r] = v.z;
            sX[kb + 3][r] = v.w;
        }
        #pragma unroll
        for (int i = 0; i < 2; i++) {
            int id = t + i * 256;
            int kk = id >> 4, c4 = (id & 15) * 4;
            *(float4*)&sWa[kk][c4] = *(const float4*)&Wm1[(kc + kk) * 64 + c4];
            *(float4*)&sWb[kk][c4] = *(const float4*)&Wm1[(64 + kc + kk) * 64 + c4];
        }
        __syncthreads();
        #pragma unroll
        for (int kk = 0; kk < 32; kk++) {
            float a[8], b[8];
            *(float4*)&a[0] = *(const float4*)&sX[kk][ty * 8];
            *(float4*)&a[4] = *(const float4*)&sX[kk][ty * 8 + 4];
            *(float4*)&b[0] = *(const float4*)&sWa[kk][tx * 4];
            *(float4*)&b[4] = *(const float4*)&sWb[kk][tx * 4];
            #pragma unroll
            for (int i2 = 0; i2 < 8; i2++)
                #pragma unroll
                for (int j = 0; j < 8; j++)
                    acc[i2][j] += a[i2] * b[j];
        }
        __syncthreads();
    }
    #pragma unroll
    for (int i2 = 0; i2 < 8; i2++) {
        int row = br + ty * 8 + i2;
        if (row < NN) {
            *(float4*)&AB[row * 128 + tx * 4]      = *(float4*)&acc[i2][0];
            *(float4*)&AB[row * 128 + 64 + tx * 4] = *(float4*)&acc[i2][4];
        }
    }
}

// ---------------- edge scatter: Acc[dst] += Hn[src] * dinv[dst] -------------
// 2 edges per thread (e, e+NE/2): two independent gather->RED chains.
__global__ void k_scatter(const float* __restrict__ Hn, const float* __restrict__ dinv,
                          const int* __restrict__ ei, float* __restrict__ Acc) {
    const int HALF = NE / 2;
    int tid = blockIdx.x * blockDim.x + threadIdx.x;
    if (tid >= HALF * 16) return;
    int p = tid >> 4, q = tid & 15;
    int e0 = p, e1 = p + HALF;
    int s0 = ei[e0],      s1 = ei[e1];
    int d0 = ei[NE + e0], d1 = ei[NE + e1];
    float n0 = dinv[d0], n1 = dinv[d1];
    float4 v0 = *(const float4*)&Hn[s0 * HID + q * 4];
    float4 v1 = *(const float4*)&Hn[s1 * HID + q * 4];
    v0.x *= n0; v0.y *= n0; v0.z *= n0; v0.w *= n0;
    v1.x *= n1; v1.y *= n1; v1.z *= n1; v1.w *= n1;
    red_add_v4(&Acc[d0 * HID + q * 4], v0);
    red_add_v4(&Acc[d1 * HID + q * 4], v1);
}

// ---------------- fused edge kernel: GEMM-structured -------------------------
// Block = 128 edges, 256 threads. Microtile: 8 edges x 4 hidden-cols.
#define EB 128
__global__ void __launch_bounds__(256)
k_edge_fused(const float* __restrict__ AB, const int* __restrict__ ei,
             const float* __restrict__ attr, const float* __restrict__ Wm1,
             const float* __restrict__ bm1, const float* __restrict__ Wm2,
             const float* __restrict__ bm2, float* __restrict__ out) {
    __shared__ float  sAt[EDIM][132];   // attr^T: [k][edge]
    __shared__ float  sWe[EDIM][64];    // Wm1 rows 128..143
    __shared__ int    ssrc[EB], sdst[EB];
    __shared__ float4 w2c0s[16], w2c1s[16], sb1v[16];
    __shared__ float  sb2[2];

    int t  = threadIdx.x;
    int E0 = blockIdx.x * EB;

    // stage attr (128 edges x 16) transposed; 2 x LDG.128 per thread
    {
        const float4* ap = (const float4*)(attr + (long)E0 * EDIM);
        #pragma unroll
        for (int j = 0; j < 2; j++) {
            float4 v = ap[t * 2 + j];
            int fidx = t * 8 + j * 4;
            int e = fidx >> 4, k = fidx & 15;
            sAt[k + 0][e] = v.x;
            sAt[k + 1][e] = v.y;
            sAt[k + 2][e] = v.z;
            sAt[k + 3][e] = v.w;
        }
    }
    // stage We (16 x 64): 1 float4 per thread
    {
        int kk = t >> 4, c4 = (t & 15) * 4;
        *(float4*)&sWe[kk][c4] = *(const float4*)&Wm1[(128 + kk) * HID + c4];
    }
    // stage edge indices
    if (t < EB) ssrc[t] = ei[E0 + t];
    else        sdst[t - EB] = ei[NE + E0 + (t - EB)];
    // stage small tables
    if (t < 16) {
        int g = t;
        w2c0s[g] = make_float4(Wm2[(4*g+0)*2],   Wm2[(4*g+1)*2],
                               Wm2[(4*g+2)*2],   Wm2[(4*g+3)*2]);
        w2c1s[g] = make_float4(Wm2[(4*g+0)*2+1], Wm2[(4*g+1)*2+1],
                               Wm2[(4*g+2)*2+1], Wm2[(4*g+3)*2+1]);
        sb1v[g]  = *(const float4*)&bm1[g * 4];
    }
    if (t < 2) sb2[t] = bm2[t];
    __syncthreads();

    int tx = t & 15, ty = t >> 4;

    // attr @ We  (K=16 dense GEMM): acc[8 edges][4 cols]
    float acc[8][4] = {};
    #pragma unroll
    for (int kk = 0; kk < EDIM; kk++) {
        float a[8], b[4];
        *(float4*)&a[0] = *(const float4*)&sAt[kk][ty * 8];
        *(float4*)&a[4] = *(const float4*)&sAt[kk][ty * 8 + 4];
        *(float4*)&b[0] = *(const float4*)&sWe[kk][tx * 4];
        #pragma unroll
        for (int i = 0; i < 8; i++)
            #pragma unroll
            for (int j = 0; j < 4; j++)
                acc[i][j] += a[i] * b[j];
    }

    float4 bias = sb1v[tx];
    float4 wc0  = w2c0s[tx];
    float4 wc1  = w2c1s[tx];
    float  b2x  = sb2[0], b2y = sb2[1];

    // epilogue: 4 edges per iteration, 8 independent gathers batched
    #pragma unroll
    for (int i = 0; i < 8; i += 4) {
        float4 A[4], B[4];
        #pragma unroll
        for (int j = 0; j < 4; j++) {
            int le = ty * 8 + i + j;
            A[j] = *(const float4*)&AB[ssrc[le] * 128 + tx * 4];
            B[j] = *(const float4*)&AB[sdst[le] * 128 + 64 + tx * 4];
        }
        float p[4], r[4];
        #pragma unroll
        for (int j = 0; j < 4; j++) {
            int ii = i + j;
            float z0 = fmaxf(acc[ii][0] + A[j].x + B[j].x + bias.x, 0.f);
            float z1 = fmaxf(acc[ii][1] + A[j].y + B[j].y + bias.y, 0.f);
            float z2 = fmaxf(acc[ii][2] + A[j].z + B[j].z + bias.z, 0.f);
            float z3 = fmaxf(acc[ii][3] + A[j].w + B[j].w + bias.w, 0.f);
            p[j] = z0 * wc0.x + z1 * wc0.y + z2 * wc0.z + z3 * wc0.w;
            r[j] = z0 * wc1.x + z1 * wc1.y + z2 * wc1.z + z3 * wc1.w;
        }
        #pragma unroll
        for (int off = 8; off; off >>= 1) {
            #pragma unroll
            for (int j = 0; j < 4; j++) {
                p[j] += __shfl_xor_sync(0xffffffffu, p[j], off, 16);
                r[j] += __shfl_xor_sync(0xffffffffu, r[j], off, 16);
            }
        }
        if (tx == 0) {
            #pragma unroll
            for (int j = 0; j < 4; j++) {
                int le = ty * 8 + i + j;
                *(float2*)&out[(E0 + le) * 2] = make_float2(p[j] + b2x, r[j] + b2y);
            }
        }
    }
}

// ---------------- launch ----------------------------------------------------
extern "C" void kernel_launch(void* const* d_in, const int* in_sizes, int n_in,
                              void* d_out, int out_size) {
    const float* x    = (const float*)d_in[0];
    const int*   ei   = (const int*)d_in[1];
    const float* attr = (const float*)d_in[2];
    const float* W1   = (const float*)d_in[3];
    const float* b1   = (const float*)d_in[4];
    const float* W2   = (const float*)d_in[5];
    const float* b2   = (const float*)d_in[6];
    const float* Wm1  = (const float*)d_in[7];
    const float* bm1  = (const float*)d_in[8];
    const float* Wm2  = (const float*)d_in[9];
    const float* bm2  = (const float*)d_in[10];
    float* out = (float*)d_out;

    float *Hn, *Acc, *AB, *dinv; int* deg;
    cudaGetSymbolAddress((void**)&Hn,   g_Hn);
    cudaGetSymbolAddress((void**)&Acc,  g_Acc);
    cudaGetSymbolAddress((void**)&AB,   g_AB);
    cudaGetSymbolAddress((void**)&deg,  g_deg);
    cudaGetSymbolAddress((void**)&dinv, g_dinv);

    const int T = 256;
    int gb_nodes = (NN + T - 1) / T;
    int gb_edges = (NE + T - 1) / T;
    int gb_sc    = (NE * 8 + T - 1) / T;   // 2 edges per thread
    int gb_gemm  = (NN + 127) / 128;
    int gb_edge  = NE / EB;   // 6250, exact

    // 1-3: degrees + dinv
    k_deg_init<<<gb_nodes, T>>>(deg);
    k_deg_count<<<gb_edges, T>>>(ei, deg);
    k_deg_inv<<<gb_nodes, T>>>(deg, dinv);

    // 4: GCN layer 1 GEMM (PROFILED LAUNCH)
    k_gemm<NDIM, false><<<gb_gemm, T>>>(x, W1, nullptr, dinv, Hn, Acc);
    k_scatter<<<gb_sc, T>>>(Hn, dinv, ei, Acc);

    // GCN layer 2
    k_gemm<HID, true><<<gb_gemm, T>>>(Acc, W2, b1, dinv, Hn, Acc);
    k_scatter<<<gb_sc, T>>>(Hn, dinv, ei, Acc);

    // combined edge-MLP partials A|B
    k_gemm_ab<<<gb_gemm, T>>>(Acc, Wm1, b2, AB);

    // fused edge MLP (GEMM-structured)
    k_edge_fused<<<gb_edge, T>>>(AB, ei, attr, Wm1, bm1, Wm2, bm2, out);
}

// round 17
// speedup vs baseline: 1.6989x; 1.0497x over previous
#include <cuda_runtime.h>

#define NN 50000
#define NE 800000
#define NDIM 128
#define HID 64
#define EDIM 16

// ---------------- scratch (device globals; no allocation allowed) ----------
__device__ __align__(16) float g_Hn[NN * HID];     // (X@W) * dinv[row]
__device__ __align__(16) float g_Acc[NN * HID];    // raw aggregation accumulator
__device__ __align__(16) float g_AB[NN * 128];     // [A | B] per node for edge MLP
__device__ int g_deg[NN];

// ---------------- vector reduction helper ----------------------------------
__device__ __forceinline__ void red_add_v4(float* p, float4 v) {
    asm volatile("red.global.add.v4.f32 [%0], {%1,%2,%3,%4};"
                 :: "l"(p), "f"(v.x), "f"(v.y), "f"(v.z), "f"(v.w)
                 : "memory");
}

// ---------------- degree kernels -------------------------------------------
__global__ void k_deg_init(int* deg) {
    int i = blockIdx.x * blockDim.x + threadIdx.x;
    if (i < NN) deg[i] = 1;   // self-loop
}
__global__ void k_deg_count(const int* __restrict__ ei, int* deg) {
    int e = blockIdx.x * blockDim.x + threadIdx.x;
    if (e < NE) atomicAdd(&deg[ei[NE + e]], 1);
}

// ---------------- GEMM: Out = [relu(X*dinv + b)] @ W[K,64] ------------------
// 128x64 tile, 256 threads, 8x4 microtile, K chunked by 32.
// IN_SCALE: input rows scaled by rsqrt(deg[row]) (deferred aggregation norm).
// Epilogue: Hn = acc * rsqrt(deg[row]) written to BOTH OutA (Hn) and OutB
// (Acc raw init = self-loop term Hn[row]).
template <int K, bool IN_RELU, bool IN_SCALE>
__global__ void __launch_bounds__(256, 3)
k_gemm(const float* __restrict__ X, const float* __restrict__ W,
       const float* __restrict__ inb, const int* __restrict__ deg,
       float* __restrict__ OutA, float* __restrict__ OutB) {
    __shared__ float sX[32][132];   // [k][row], 16B-aligned stride
    __shared__ float sW[32][64];    // [k][col]
    int t  = threadIdx.x;
    int br = blockIdx.x * 128;
    int tx = t & 15, ty = t >> 4;
    float acc[8][4] = {};

    for (int kc = 0; kc < K; kc += 32) {
        #pragma unroll
        for (int i = 0; i < 4; i++) {
            int id = t + i * 256;
            int r  = id >> 3;
            int kb = (id & 7) * 4;
            int row = br + r;
            float4 v = make_float4(0.f, 0.f, 0.f, 0.f);
            if (row < NN) {
                v = *(const float4*)&X[row * K + kc + kb];
                if (IN_SCALE) {
                    float d = rsqrtf((float)deg[row]);
                    v.x *= d; v.y *= d; v.z *= d; v.w *= d;
                }
                if (IN_RELU) {
                    v.x = fmaxf(v.x + inb[kc + kb + 0], 0.f);
                    v.y = fmaxf(v.y + inb[kc + kb + 1], 0.f);
                    v.z = fmaxf(v.z + inb[kc + kb + 2], 0.f);
                    v.w = fmaxf(v.w + inb[kc + kb + 3], 0.f);
                }
            }
            sX[kb + 0][r] = v.x;
            sX[kb + 1][r] = v.y;
            sX[kb + 2][r] = v.z;
            sX[kb + 3][r] = v.w;
        }
        #pragma unroll
        for (int i = 0; i < 2; i++) {
            int id = t + i * 256;
            int kk = id >> 4, c4 = (id & 15) * 4;
            *(float4*)&sW[kk][c4] = *(const float4*)&W[(kc + kk) * 64 + c4];
        }
        __syncthreads();
        #pragma unroll
        for (int kk = 0; kk < 32; kk++) {
            float a[8], b[4];
            *(float4*)&a[0] = *(const float4*)&sX[kk][ty * 8];
            *(float4*)&a[4] = *(const float4*)&sX[kk][ty * 8 + 4];
            *(float4*)&b[0] = *(const float4*)&sW[kk][tx * 4];
            #pragma unroll
            for (int i2 = 0; i2 < 8; i2++)
                #pragma unroll
                for (int j = 0; j < 4; j++)
                    acc[i2][j] += a[i2] * b[j];
        }
        __syncthreads();
    }
    #pragma unroll
    for (int i2 = 0; i2 < 8; i2++) {
        int row = br + ty * 8 + i2;
        if (row < NN) {
            float d = rsqrtf((float)deg[row]);
            float4 hn = make_float4(acc[i2][0] * d, acc[i2][1] * d,
                                    acc[i2][2] * d, acc[i2][3] * d);
            *(float4*)&OutA[row * HID + tx * 4] = hn;   // Hn
            *(float4*)&OutB[row * HID + tx * 4] = hn;   // Acc raw (self term)
        }
    }
}

// ---------------- combined AB GEMM: AB = relu(Acc*dinv + b2) @ [Wm1_A|Wm1_B]
__global__ void __launch_bounds__(256, 2)
k_gemm_ab(const float* __restrict__ X, const float* __restrict__ Wm1,
          const float* __restrict__ inb, const int* __restrict__ deg,
          float* __restrict__ AB) {
    __shared__ float sX[32][132];
    __shared__ float sWa[32][64];
    __shared__ float sWb[32][64];
    int t  = threadIdx.x;
    int br = blockIdx.x * 128;
    int tx = t & 15, ty = t >> 4;
    float acc[8][8] = {};

    for (int kc = 0; kc < HID; kc += 32) {
        #pragma unroll
        for (int i = 0; i < 4; i++) {
            int id = t + i * 256;
            int r  = id >> 3;
            int kb = (id & 7) * 4;
            int row = br + r;
            float4 v = make_float4(0.f, 0.f, 0.f, 0.f);
            if (row < NN) {
                v = *(const float4*)&X[row * HID + kc + kb];
                float d = rsqrtf((float)deg[row]);
                v.x = fmaxf(v.x * d + inb[kc + kb + 0], 0.f);
                v.y = fmaxf(v.y * d + inb[kc + kb + 1], 0.f);
                v.z = fmaxf(v.z * d + inb[kc + kb + 2], 0.f);
                v.w = fmaxf(v.w * d + inb[kc + kb + 3], 0.f);
            }
            sX[kb + 0][r] = v.x;
            sX[kb + 1][r] = v.y;
            sX[kb + 2][r] = v.z;
            sX[kb + 3][r] = v.w;
        }
        #pragma unroll
        for (int i = 0; i < 2; i++) {
            int id = t + i * 256;
            int kk = id >> 4, c4 = (id & 15) * 4;
            *(float4*)&sWa[kk][c4] = *(const float4*)&Wm1[(kc + kk) * 64 + c4];
            *(float4*)&sWb[kk][c4] = *(const float4*)&Wm1[(64 + kc + kk) * 64 + c4];
        }
        __syncthreads();
        #pragma unroll
        for (int kk = 0; kk < 32; kk++) {
            float a[8], b[8];
            *(float4*)&a[0] = *(const float4*)&sX[kk][ty * 8];
            *(float4*)&a[4] = *(const float4*)&sX[kk][ty * 8 + 4];
            *(float4*)&b[0] = *(const float4*)&sWa[kk][tx * 4];
            *(float4*)&b[4] = *(const float4*)&sWb[kk][tx * 4];
            #pragma unroll
            for (int i2 = 0; i2 < 8; i2++)
                #pragma unroll
                for (int j = 0; j < 8; j++)
                    acc[i2][j] += a[i2] * b[j];
        }
        __syncthreads();
    }
    #pragma unroll
    for (int i2 = 0; i2 < 8; i2++) {
        int row = br + ty * 8 + i2;
        if (row < NN) {
            *(float4*)&AB[row * 128 + tx * 4]      = *(float4*)&acc[i2][0];
            *(float4*)&AB[row * 128 + 64 + tx * 4] = *(float4*)&acc[i2][4];
        }
    }
}

// ---------------- edge scatter: Acc[dst] += Hn[src] (pure RED) ---------------
// 2 edges per thread (e, e+NE/2): two independent gather->RED chains.
__global__ void k_scatter(const float* __restrict__ Hn, const int* __restrict__ ei,
                          float* __restrict__ Acc) {
    const int HALF = NE / 2;
    int tid = blockIdx.x * blockDim.x + threadIdx.x;
    if (tid >= HALF * 16) return;
    int p = tid >> 4, q = tid & 15;
    int s0 = ei[p],        s1 = ei[p + HALF];
    int d0 = ei[NE + p],   d1 = ei[NE + p + HALF];
    float4 v0 = *(const float4*)&Hn[s0 * HID + q * 4];
    float4 v1 = *(const float4*)&Hn[s1 * HID + q * 4];
    red_add_v4(&Acc[d0 * HID + q * 4], v0);
    red_add_v4(&Acc[d1 * HID + q * 4], v1);
}

// ---------------- fused edge kernel: GEMM-structured -------------------------
// Block = 128 edges, 256 threads. Microtile: 8 edges x 4 hidden-cols.
#define EB 128
__global__ void __launch_bounds__(256)
k_edge_fused(const float* __restrict__ AB, const int* __restrict__ ei,
             const float* __restrict__ attr, const float* __restrict__ Wm1,
             const float* __restrict__ bm1, const float* __restrict__ Wm2,
             const float* __restrict__ bm2, float* __restrict__ out) {
    __shared__ float  sAt[EDIM][132];   // attr^T: [k][edge]
    __shared__ float  sWe[EDIM][64];    // Wm1 rows 128..143
    __shared__ int    ssrc[EB], sdst[EB];
    __shared__ float4 w2c0s[16], w2c1s[16], sb1v[16];
    __shared__ float  sb2[2];

    int t  = threadIdx.x;
    int E0 = blockIdx.x * EB;

    {
        const float4* ap = (const float4*)(attr + (long)E0 * EDIM);
        #pragma unroll
        for (int j = 0; j < 2; j++) {
            float4 v = ap[t * 2 + j];
            int fidx = t * 8 + j * 4;
            int e = fidx >> 4, k = fidx & 15;
            sAt[k + 0][e] = v.x;
            sAt[k + 1][e] = v.y;
            sAt[k + 2][e] = v.z;
            sAt[k + 3][e] = v.w;
        }
    }
    {
        int kk = t >> 4, c4 = (t & 15) * 4;
        *(float4*)&sWe[kk][c4] = *(const float4*)&Wm1[(128 + kk) * HID + c4];
    }
    if (t < EB) ssrc[t] = ei[E0 + t];
    else        sdst[t - EB] = ei[NE + E0 + (t - EB)];
    if (t < 16) {
        int g = t;
        w2c0s[g] = make_float4(Wm2[(4*g+0)*2],   Wm2[(4*g+1)*2],
                               Wm2[(4*g+2)*2],   Wm2[(4*g+3)*2]);
        w2c1s[g] = make_float4(Wm2[(4*g+0)*2+1], Wm2[(4*g+1)*2+1],
                               Wm2[(4*g+2)*2+1], Wm2[(4*g+3)*2+1]);
        sb1v[g]  = *(const float4*)&bm1[g * 4];
    }
    if (t < 2) sb2[t] = bm2[t];
    __syncthreads();

    int tx = t & 15, ty = t >> 4;

    float acc[8][4] = {};
    #pragma unroll
    for (int kk = 0; kk < EDIM; kk++) {
        float a[8], b[4];
        *(float4*)&a[0] = *(const float4*)&sAt[kk][ty * 8];
        *(float4*)&a[4] = *(const float4*)&sAt[kk][ty * 8 + 4];
        *(float4*)&b[0] = *(const float4*)&sWe[kk][tx * 4];
        #pragma unroll
        for (int i = 0; i < 8; i++)
            #pragma unroll
            for (int j = 0; j < 4; j++)
                acc[i][j] += a[i] * b[j];
    }

    float4 bias = sb1v[tx];
    float4 wc0  = w2c0s[tx];
    float4 wc1  = w2c1s[tx];
    float  b2x  = sb2[0], b2y = sb2[1];

    #pragma unroll
    for (int i = 0; i < 8; i += 4) {
        float4 A[4], B[4];
        #pragma unroll
        for (int j = 0; j < 4; j++) {
            int le = ty * 8 + i + j;
            A[j] = *(const float4*)&AB[ssrc[le] * 128 + tx * 4];
            B[j] = *(const float4*)&AB[sdst[le] * 128 + 64 + tx * 4];
        }
        float p[4], r[4];
        #pragma unroll
        for (int j = 0; j < 4; j++) {
            int ii = i + j;
            float z0 = fmaxf(acc[ii][0] + A[j].x + B[j].x + bias.x, 0.f);
            float z1 = fmaxf(acc[ii][1] + A[j].y + B[j].y + bias.y, 0.f);
            float z2 = fmaxf(acc[ii][2] + A[j].z + B[j].z + bias.z, 0.f);
            float z3 = fmaxf(acc[ii][3] + A[j].w + B[j].w + bias.w, 0.f);
            p[j] = z0 * wc0.x + z1 * wc0.y + z2 * wc0.z + z3 * wc0.w;
            r[j] = z0 * wc1.x + z1 * wc1.y + z2 * wc1.z + z3 * wc1.w;
        }
        #pragma unroll
        for (int off = 8; off; off >>= 1) {
            #pragma unroll
            for (int j = 0; j < 4; j++) {
                p[j] += __shfl_xor_sync(0xffffffffu, p[j], off, 16);
                r[j] += __shfl_xor_sync(0xffffffffu, r[j], off, 16);
            }
        }
        if (tx == 0) {
            #pragma unroll
            for (int j = 0; j < 4; j++) {
                int le = ty * 8 + i + j;
                *(float2*)&out[(E0 + le) * 2] = make_float2(p[j] + b2x, r[j] + b2y);
            }
        }
    }
}

// ---------------- launch ----------------------------------------------------
extern "C" void kernel_launch(void* const* d_in, const int* in_sizes, int n_in,
                              void* d_out, int out_size) {
    const float* x    = (const float*)d_in[0];
    const int*   ei   = (const int*)d_in[1];
    const float* attr = (const float*)d_in[2];
    const float* W1   = (const float*)d_in[3];
    const float* b1   = (const float*)d_in[4];
    const float* W2   = (const float*)d_in[5];
    const float* b2   = (const float*)d_in[6];
    const float* Wm1  = (const float*)d_in[7];
    const float* bm1  = (const float*)d_in[8];
    const float* Wm2  = (const float*)d_in[9];
    const float* bm2  = (const float*)d_in[10];
    float* out = (float*)d_out;

    float *Hn, *Acc, *AB; int* deg;
    cudaGetSymbolAddress((void**)&Hn,  g_Hn);
    cudaGetSymbolAddress((void**)&Acc, g_Acc);
    cudaGetSymbolAddress((void**)&AB,  g_AB);
    cudaGetSymbolAddress((void**)&deg, g_deg);

    const int T = 256;
    int gb_nodes = (NN + T - 1) / T;
    int gb_edges = (NE + T - 1) / T;
    int gb_sc    = (NE * 8 + T - 1) / T;   // 2 edges per thread
    int gb_gemm  = (NN + 127) / 128;
    int gb_edge  = NE / EB;   // 6250, exact

    // 1,2: degrees (dinv never materialized; consumers rsqrt on the fly)
    k_deg_init<<<gb_nodes, T>>>(deg);
    k_deg_count<<<gb_edges, T>>>(ei, deg);

    // 3: GCN layer 1 GEMM (Hn = (x@W1)*dinv; Acc = Hn raw self term)
    k_gemm<NDIM, false, false><<<gb_gemm, T>>>(x, W1, nullptr, deg, Hn, Acc);
    // 4: pure-RED scatter (PROFILED LAUNCH)
    k_scatter<<<gb_sc, T>>>(Hn, ei, Acc);

    // 5,6: GCN layer 2 (input scaled by dinv + relu + bias)
    k_gemm<HID, true, true><<<gb_gemm, T>>>(Acc, W2, b1, deg, Hn, Acc);
    k_scatter<<<gb_sc, T>>>(Hn, ei, Acc);

    // 7: combined edge-MLP partials A|B (input scaled + relu + bias)
    k_gemm_ab<<<gb_gemm, T>>>(Acc, Wm1, b2, deg, AB);

    // 8: fused edge MLP (GEMM-structured)
    k_edge_fused<<<gb_edge, T>>>(AB, ei, attr, Wm1, bm1, Wm2, bm2, out);
}